// round 11
// baseline (speedup 1.0000x reference)
#include <cuda_runtime.h>
#include <cuda_bf16.h>
#include <math.h>

// Problem constants: B=4, S=1024, D=1024, H=16, Hd=64
#define PB 4
#define PS 1024
#define PD 1024
#define PH 16
#define PHD 64
#define BS (PB * PS)
#define QKV_N (3 * PD)
#define ATTN_OUT_ELEMS (4194304ull)
#define ATTN_W_ELEMS   (67108864ull)

__device__ float g_qkv[BS * QKV_N];
__device__ float g_ctx[BS * PD];
__device__ float g_wscratch[ATTN_W_ELEMS];

__device__ __forceinline__ unsigned f2tf32(float f) {
    unsigned u;
    asm("cvt.rna.tf32.f32 %0, %1;" : "=r"(u) : "f"(f));
    return u;
}

__device__ __forceinline__ void mma16n8k8(float c[4], const unsigned a[4],
                                          const unsigned b[2]) {
    asm volatile(
        "mma.sync.aligned.m16n8k8.row.col.f32.tf32.tf32.f32 "
        "{%0,%1,%2,%3}, {%4,%5,%6,%7}, {%8,%9}, {%0,%1,%2,%3};\n"
        : "+f"(c[0]), "+f"(c[1]), "+f"(c[2]), "+f"(c[3])
        : "r"(a[0]), "r"(a[1]), "r"(a[2]), "r"(a[3]),
          "r"(b[0]), "r"(b[1]));
}

__device__ __forceinline__ float qmax(float v) {
    v = fmaxf(v, __shfl_xor_sync(0xffffffffu, v, 1));
    v = fmaxf(v, __shfl_xor_sync(0xffffffffu, v, 2));
    return v;
}
__device__ __forceinline__ float qsum(float v) {
    v += __shfl_xor_sync(0xffffffffu, v, 1);
    v += __shfl_xor_sync(0xffffffffu, v, 2);
    return v;
}

// ---------------------------------------------------------------------------
// K1/K5: SGEMM tf32, 128x128 tile, BK=16, double-buffered (1 barrier/iter).
// Operands staged in FRAGMENT-PACKED layout:
//   A: Ap[buf][wr][ks][mt][chunk][val], chunk=((grp^2tig)&7)+8*tig,
//      val'=val^(2*(mt&1))  -> warp fragment = one LDS.128 per (ks,mt).
//   B: Bp[buf][wc][ks][nt*66 + lane*2 + khalf] -> one LDS.64 per (ks,nt).
// All staging STS and fragment LDS verified bank-conflict-free.
// ---------------------------------------------------------------------------
__global__ __launch_bounds__(256) void sgemm_tf32(
    const float* __restrict__ A, const float* __restrict__ B,
    const float* __restrict__ bias, float* __restrict__ C,
    int M, int N, int K)
{
    __shared__ unsigned Ap[2][2][2][4][32][4];   // 16 KB
    __shared__ unsigned Bp[2][4][2][276];        // ~17.3 KB

    int tid = threadIdx.x, lane = tid & 31, wid = tid >> 5;
    int grp = lane >> 2, tig = lane & 3;
    int wr_ = wid >> 2, wc_ = wid & 3;
    int m0 = blockIdx.y * 128, n0 = blockIdx.x * 128;
    int chA = ((grp ^ (2 * tig)) & 7) + 8 * tig;

    float c[4][4][4];
#pragma unroll
    for (int mt = 0; mt < 4; mt++)
#pragma unroll
        for (int nt = 0; nt < 4; nt++)
#pragma unroll
            for (int i = 0; i < 4; i++) c[mt][nt][i] = 0.f;

    // --- staging decomposition ---
    int ar = tid & 127, ac = (tid >> 7) * 8;        // A: row, k-base (ks fixed)
    int s_mm = ar & 63;
    int s_wr = ar >> 6, s_mt = s_mm >> 4;
    int s_half = (s_mm >> 3) & 1, s_grp = s_mm & 7;
    int s_ks = ac >> 3;
    int s_vx = 2 * (s_mt & 1);
    int u = tid >> 4;                                // B k-row remap
    int kB = ((u & 1) << 2) | ((u >> 1) & 3) | (u & 8);
    int b_ks = kB >> 3, b_tig = kB & 3, b_kh = (kB >> 2) & 1;
    int bn = (tid & 15) * 8;
    int s_wc = bn >> 5, s_nt = (bn >> 3) & 3;

    const float* Ag = A + (size_t)(m0 + ar) * K + ac;
    const float* Bg = B + (size_t)kB * N + n0 + bn;

    float4 pa0 = *(const float4*)(Ag);
    float4 pa1 = *(const float4*)(Ag + 4);
    float4 pb0 = *(const float4*)(Bg);
    float4 pb1 = *(const float4*)(Bg + 4);

    int T = K >> 4;
    for (int t = 0; t < T; t++) {
        int buf = t & 1;
        {   // stage A (8 scattered STS.32, CF)
            unsigned* ad = &Ap[buf][s_wr][s_ks][s_mt][0][0];
            float av[8] = {pa0.x, pa0.y, pa0.z, pa0.w,
                           pa1.x, pa1.y, pa1.z, pa1.w};
#pragma unroll
            for (int j = 0; j < 8; j++) {
                int tg = j & 3, kh = j >> 2;
                int ch = ((s_grp ^ (2 * tg)) & 7) + 8 * tg;
                int vl = (s_half + 2 * kh) ^ s_vx;
                ad[ch * 4 + vl] = f2tf32(av[j]);
            }
            // stage B (8 scattered STS.32, CF)
            unsigned* bd = &Bp[buf][s_wc][b_ks][0];
            float bv[8] = {pb0.x, pb0.y, pb0.z, pb0.w,
                           pb1.x, pb1.y, pb1.z, pb1.w};
#pragma unroll
            for (int j = 0; j < 8; j++)
                bd[s_nt * 66 + (j * 4 + b_tig) * 2 + b_kh] = f2tf32(bv[j]);
        }
        __syncthreads();

        if (t + 1 < T) {     // prefetch next tile (hidden behind mma)
            int kn = (t + 1) * 16;
            pa0 = *(const float4*)(Ag + kn);
            pa1 = *(const float4*)(Ag + kn + 4);
            pb0 = *(const float4*)(Bg + (size_t)kn * N);
            pb1 = *(const float4*)(Bg + (size_t)kn * N + 4);
        }

#pragma unroll
        for (int ks = 0; ks < 2; ks++) {
            unsigned af[4][4], bf[4][2];
#pragma unroll
            for (int mt = 0; mt < 4; mt++) {
                uint4 v = *(const uint4*)&Ap[buf][wr_][ks][mt][chA][0];
                if (mt & 1) { af[mt][0] = v.z; af[mt][1] = v.w;
                              af[mt][2] = v.x; af[mt][3] = v.y; }
                else        { af[mt][0] = v.x; af[mt][1] = v.y;
                              af[mt][2] = v.z; af[mt][3] = v.w; }
            }
#pragma unroll
            for (int nt = 0; nt < 4; nt++) {
                uint2 v = *(const uint2*)&Bp[buf][wc_][ks][nt * 66 + lane * 2];
                bf[nt][0] = v.x; bf[nt][1] = v.y;
            }
#pragma unroll
            for (int mt = 0; mt < 4; mt++)
#pragma unroll
                for (int nt = 0; nt < 4; nt++)
                    mma16n8k8(c[mt][nt], af[mt], bf[nt]);
        }
        // no trailing barrier: next STS targets the other buffer
    }

#pragma unroll
    for (int mt = 0; mt < 4; mt++) {
        int r0 = m0 + wr_ * 64 + mt * 16 + grp;
#pragma unroll
        for (int nt = 0; nt < 4; nt++) {
            int col = n0 + wc_ * 32 + nt * 8 + tig * 2;
            float2 bv = *(const float2*)(bias + col);
            *(float2*)(C + (size_t)r0 * N + col) =
                make_float2(c[mt][nt][0] + bv.x, c[mt][nt][1] + bv.y);
            *(float2*)(C + (size_t)(r0 + 8) * N + col) =
                make_float2(c[mt][nt][2] + bv.x, c[mt][nt][3] + bv.y);
        }
    }
}

// ---------------------------------------------------------------------------
// Fused attention: scores + softmax + AV (unchanged from R5).
// ---------------------------------------------------------------------------
__global__ __launch_bounds__(256, 2) void attn_fused(
    const float* __restrict__ qkv, float* __restrict__ w,
    float* __restrict__ ctx)
{
    __shared__ unsigned Ks[64][68];
    __shared__ unsigned Vs[64][72];

    int tid = threadIdx.x, lane = tid & 31, wid = tid >> 5;
    int grp = lane >> 2, tig = lane & 3;
    int qt = 7 - blockIdx.x;
    int q0 = qt * 128;
    int ntiles = qt * 2 + 2;
    int bh = blockIdx.y;
    int b = bh >> 4, h = bh & 15;

    int row0 = wid * 16 + grp;
    int gq0 = q0 + row0, gq1 = gq0 + 8;

    const float* Q0 = qkv + (size_t)(b * PS + gq0) * QKV_N + h * PHD;
    const float* Q1 = Q0 + 8 * QKV_N;
    unsigned qa[8][4];
#pragma unroll
    for (int kd = 0; kd < 8; kd++) {
        qa[kd][0] = f2tf32(Q0[kd * 8 + tig] * 0.125f);
        qa[kd][1] = f2tf32(Q1[kd * 8 + tig] * 0.125f);
        qa[kd][2] = f2tf32(Q0[kd * 8 + tig + 4] * 0.125f);
        qa[kd][3] = f2tf32(Q1[kd * 8 + tig + 4] * 0.125f);
    }

    int kr = tid >> 2, kc = (tid & 3) * 16;
    const float* Kb = qkv + (size_t)(b * PS + kr) * QKV_N + PD + h * PHD + kc;
    const float* Vb = Kb + PD;

    float m0 = -INFINITY, m1 = -INFINITY, l0 = 0.f, l1 = 0.f;

    // ---------------- Pass 1: row stats ----------------
    float4 pk[4];
#pragma unroll
    for (int i = 0; i < 4; i++) pk[i] = *(const float4*)(Kb + i * 4);

    for (int t = 0; t < ntiles; t++) {
#pragma unroll
        for (int i = 0; i < 4; i++) {
            Ks[kr][kc + i * 4 + 0] = f2tf32(pk[i].x);
            Ks[kr][kc + i * 4 + 1] = f2tf32(pk[i].y);
            Ks[kr][kc + i * 4 + 2] = f2tf32(pk[i].z);
            Ks[kr][kc + i * 4 + 3] = f2tf32(pk[i].w);
        }
        __syncthreads();
        if (t + 1 < ntiles) {
#pragma unroll
            for (int i = 0; i < 4; i++)
                pk[i] = *(const float4*)(Kb + (size_t)(t + 1) * 64 * QKV_N + i * 4);
        }

        float c[8][4];
#pragma unroll
        for (int nt = 0; nt < 8; nt++)
#pragma unroll
            for (int i = 0; i < 4; i++) c[nt][i] = 0.f;
#pragma unroll
        for (int kd = 0; kd < 8; kd++) {
            int kb = kd * 8;
#pragma unroll
            for (int nt = 0; nt < 8; nt++) {
                unsigned bf[2] = { Ks[nt * 8 + grp][kb + tig],
                                   Ks[nt * 8 + grp][kb + tig + 4] };
                mma16n8k8(c[nt], qa[kd], bf);
            }
        }

        int kt0 = t * 64;
        if (t + 2 >= ntiles) {
#pragma unroll
            for (int nt = 0; nt < 8; nt++) {
                int cc = kt0 + nt * 8 + tig * 2;
                if (cc > gq0)     c[nt][0] = -INFINITY;
                if (cc + 1 > gq0) c[nt][1] = -INFINITY;
                if (cc > gq1)     c[nt][2] = -INFINITY;
                if (cc + 1 > gq1) c[nt][3] = -INFINITY;
            }
        }

        float tm0 = -INFINITY, tm1 = -INFINITY;
#pragma unroll
        for (int nt = 0; nt < 8; nt++) {
            tm0 = fmaxf(tm0, fmaxf(c[nt][0], c[nt][1]));
            tm1 = fmaxf(tm1, fmaxf(c[nt][2], c[nt][3]));
        }
        tm0 = qmax(tm0); tm1 = qmax(tm1);
        float nm0 = fmaxf(m0, tm0), nm1 = fmaxf(m1, tm1);
        float s0 = 0.f, s1 = 0.f;
#pragma unroll
        for (int nt = 0; nt < 8; nt++) {
            s0 += __expf(c[nt][0] - nm0) + __expf(c[nt][1] - nm0);
            s1 += __expf(c[nt][2] - nm1) + __expf(c[nt][3] - nm1);
        }
        s0 = qsum(s0); s1 = qsum(s1);
        l0 = l0 * __expf(m0 - nm0) + s0;
        l1 = l1 * __expf(m1 - nm1) + s1;
        m0 = nm0; m1 = nm1;
        __syncthreads();
    }

    float inv0 = 1.f / l0, inv1 = 1.f / l1;

    // ---------------- Pass 2: emit weights + AV ----------------
    float o[8][4];
#pragma unroll
    for (int nt = 0; nt < 8; nt++)
#pragma unroll
        for (int i = 0; i < 4; i++) o[nt][i] = 0.f;

    float* wr0 = w + (size_t)(bh * PS + gq0) * PS;
    float* wr1 = wr0 + 8 * PS;
    int base = lane & ~3;

    for (int t = 0; t < ntiles; t++) {
#pragma unroll
        for (int i = 0; i < 4; i++) {
            float4 kv = *(const float4*)(Kb + (size_t)t * 64 * QKV_N + i * 4);
            float4 vv = *(const float4*)(Vb + (size_t)t * 64 * QKV_N + i * 4);
            Ks[kr][kc + i * 4 + 0] = f2tf32(kv.x);
            Ks[kr][kc + i * 4 + 1] = f2tf32(kv.y);
            Ks[kr][kc + i * 4 + 2] = f2tf32(kv.z);
            Ks[kr][kc + i * 4 + 3] = f2tf32(kv.w);
            Vs[kr][kc + i * 4 + 0] = f2tf32(vv.x);
            Vs[kr][kc + i * 4 + 1] = f2tf32(vv.y);
            Vs[kr][kc + i * 4 + 2] = f2tf32(vv.z);
            Vs[kr][kc + i * 4 + 3] = f2tf32(vv.w);
        }
        __syncthreads();

        float c[8][4];
#pragma unroll
        for (int nt = 0; nt < 8; nt++)
#pragma unroll
            for (int i = 0; i < 4; i++) c[nt][i] = 0.f;
#pragma unroll
        for (int kd = 0; kd < 8; kd++) {
            int kb = kd * 8;
#pragma unroll
            for (int nt = 0; nt < 8; nt++) {
                unsigned bf[2] = { Ks[nt * 8 + grp][kb + tig],
                                   Ks[nt * 8 + grp][kb + tig + 4] };
                mma16n8k8(c[nt], qa[kd], bf);
            }
        }

        int kt0 = t * 64;
        bool diag = (t + 2 >= ntiles);

#pragma unroll
        for (int nt = 0; nt < 8; nt++) {
            int cc = kt0 + nt * 8 + tig * 2;
            float p0 = __expf(c[nt][0] - m0) * inv0;
            float p1 = __expf(c[nt][1] - m0) * inv0;
            float p2 = __expf(c[nt][2] - m1) * inv1;
            float p3 = __expf(c[nt][3] - m1) * inv1;
            if (diag) {
                if (cc > gq0)     p0 = 0.f;
                if (cc + 1 > gq0) p1 = 0.f;
                if (cc > gq1)     p2 = 0.f;
                if (cc + 1 > gq1) p3 = 0.f;
            }
            *(float2*)(wr0 + cc) = make_float2(p0, p1);
            *(float2*)(wr1 + cc) = make_float2(p2, p3);

            unsigned u0 = f2tf32(p0), u1 = f2tf32(p1);
            unsigned u2 = f2tf32(p2), u3 = f2tf32(p3);
            int s0l = base + (tig >> 1);
            int s1l = s0l + 2;
            unsigned e0 = __shfl_sync(0xffffffffu, u0, s0l);
            unsigned f0 = __shfl_sync(0xffffffffu, u1, s0l);
            unsigned e1 = __shfl_sync(0xffffffffu, u2, s0l);
            unsigned f1 = __shfl_sync(0xffffffffu, u3, s0l);
            unsigned e2 = __shfl_sync(0xffffffffu, u0, s1l);
            unsigned f2 = __shfl_sync(0xffffffffu, u1, s1l);
            unsigned e3 = __shfl_sync(0xffffffffu, u2, s1l);
            unsigned f3 = __shfl_sync(0xffffffffu, u3, s1l);
            bool odd = (tig & 1);
            unsigned a[4];
            a[0] = odd ? f0 : e0;
            a[1] = odd ? f1 : e1;
            a[2] = odd ? f2 : e2;
            a[3] = odd ? f3 : e3;

#pragma unroll
            for (int ntd = 0; ntd < 8; ntd++) {
                unsigned bf[2] = { Vs[nt * 8 + tig][ntd * 8 + grp],
                                   Vs[nt * 8 + tig + 4][ntd * 8 + grp] };
                mma16n8k8(o[ntd], a, bf);
            }
        }
        __syncthreads();
    }

    float* c0p = ctx + (size_t)(b * PS + gq0) * PD + h * PHD;
    float* c1p = c0p + 8 * PD;
#pragma unroll
    for (int ntd = 0; ntd < 8; ntd++) {
        int col = ntd * 8 + tig * 2;
        *(float2*)(c0p + col) = make_float2(o[ntd][0], o[ntd][1]);
        *(float2*)(c1p + col) = make_float2(o[ntd][2], o[ntd][3]);
    }

    int zc = q0 + 128;
    int nz4 = (PS - zc) >> 2;
    if (nz4 > 0) {
        float4 z = make_float4(0.f, 0.f, 0.f, 0.f);
        for (int i = tid; i < 128 * nz4; i += 256) {
            int r = i / nz4, c4 = i - r * nz4;
            *(float4*)(w + (size_t)(bh * PS + q0 + r) * PS + zc + c4 * 4) = z;
        }
    }
}

// ---------------------------------------------------------------------------
extern "C" void kernel_launch(void* const* d_in, const int* in_sizes, int n_in,
                              void* d_out, int out_size)
{
    const float* hidden = (const float*)d_in[0];
    const float* W_attn = (const float*)d_in[1];
    const float* b_attn = (const float*)d_in[2];
    const float* W_proj = (const float*)d_in[3];
    const float* b_proj = (const float*)d_in[4];
    float* out = (float*)d_out;

    float *qkv, *ctx, *wscr;
    cudaGetSymbolAddress((void**)&qkv, g_qkv);
    cudaGetSymbolAddress((void**)&ctx, g_ctx);
    cudaGetSymbolAddress((void**)&wscr, g_wscratch);

    float* attn_out = out;
    float* wptr;
    if ((unsigned long long)out_size >= ATTN_OUT_ELEMS + ATTN_W_ELEMS) {
        wptr = out + ATTN_OUT_ELEMS;
    } else if ((unsigned long long)out_size == ATTN_W_ELEMS) {
        wptr = out;
        attn_out = ctx;
    } else {
        wptr = wscr;
    }

    sgemm_tf32<<<dim3(QKV_N / 128, BS / 128), 256>>>(
        hidden, W_attn, b_attn, qkv, BS, QKV_N, PD);

    attn_fused<<<dim3(8, PB * PH), 256>>>(qkv, wptr, ctx);

    sgemm_tf32<<<dim3(PD / 128, BS / 128), 256>>>(
        ctx, W_proj, b_proj, attn_out, BS, PD, PD);
}

// round 14
// speedup vs baseline: 1.1239x; 1.1239x over previous
#include <cuda_runtime.h>
#include <cuda_bf16.h>
#include <math.h>

// Problem constants: B=4, S=1024, D=1024, H=16, Hd=64
#define PB 4
#define PS 1024
#define PD 1024
#define PH 16
#define PHD 64
#define BS (PB * PS)
#define QKV_N (3 * PD)
#define ATTN_OUT_ELEMS (4194304ull)
#define ATTN_W_ELEMS   (67108864ull)

__device__ float g_qkv[BS * QKV_N];
__device__ float g_ctx[BS * PD];
__device__ float g_wscratch[ATTN_W_ELEMS];

__device__ __forceinline__ unsigned f2tf32(float f) {
    unsigned u;
    asm("cvt.rna.tf32.f32 %0, %1;" : "=r"(u) : "f"(f));
    return u;
}

__device__ __forceinline__ void mma16n8k8(float c[4], const unsigned a[4],
                                          const unsigned b[2]) {
    asm volatile(
        "mma.sync.aligned.m16n8k8.row.col.f32.tf32.tf32.f32 "
        "{%0,%1,%2,%3}, {%4,%5,%6,%7}, {%8,%9}, {%0,%1,%2,%3};\n"
        : "+f"(c[0]), "+f"(c[1]), "+f"(c[2]), "+f"(c[3])
        : "r"(a[0]), "r"(a[1]), "r"(a[2]), "r"(a[3]),
          "r"(b[0]), "r"(b[1]));
}

__device__ __forceinline__ float qmax(float v) {
    v = fmaxf(v, __shfl_xor_sync(0xffffffffu, v, 1));
    v = fmaxf(v, __shfl_xor_sync(0xffffffffu, v, 2));
    return v;
}
__device__ __forceinline__ float qsum(float v) {
    v += __shfl_xor_sync(0xffffffffu, v, 1);
    v += __shfl_xor_sync(0xffffffffu, v, 2);
    return v;
}

// ---------------------------------------------------------------------------
// K1/K5: SGEMM tf32, 128x128 tile, BK=16.
// R5 layout/fragment path (regs ~117, 2 CTAs/SM) + double-buffered smem with
// ONE barrier per iteration. launch_bounds(256,2) pins >=2 CTAs/SM.
// ---------------------------------------------------------------------------
__global__ __launch_bounds__(256, 2) void sgemm_tf32(
    const float* __restrict__ A, const float* __restrict__ B,
    const float* __restrict__ bias, float* __restrict__ C,
    int M, int N, int K)
{
    __shared__ unsigned As[2][16][136];   // [buf][k][m]
    __shared__ unsigned Bs[2][16][136];   // [buf][k][n]

    int tid = threadIdx.x, lane = tid & 31, wid = tid >> 5;
    int wm = (wid >> 2) * 64, wn = (wid & 3) * 32;
    int m0 = blockIdx.y * 128, n0 = blockIdx.x * 128;
    int grp = lane >> 2, tig = lane & 3;

    float c[4][4][4];
#pragma unroll
    for (int mt = 0; mt < 4; mt++)
#pragma unroll
        for (int nt = 0; nt < 4; nt++)
#pragma unroll
            for (int i = 0; i < 4; i++) c[mt][nt][i] = 0.f;

    int ar = tid & 127, ac = (tid >> 7) * 8;   // 32 consecutive rows per warp
    int bk = tid >> 4, bn = (tid & 15) * 8;
    const float* Ap = A + (size_t)(m0 + ar) * K + ac;
    const float* Bp = B + (size_t)bk * N + n0 + bn;

    float4 pa0 = *(const float4*)(Ap);
    float4 pa1 = *(const float4*)(Ap + 4);
    float4 pb0 = *(const float4*)(Bp);
    float4 pb1 = *(const float4*)(Bp + 4);

    int T = K >> 4;
    for (int t = 0; t < T; t++) {
        int buf = t & 1;
        As[buf][ac + 0][ar] = f2tf32(pa0.x); As[buf][ac + 1][ar] = f2tf32(pa0.y);
        As[buf][ac + 2][ar] = f2tf32(pa0.z); As[buf][ac + 3][ar] = f2tf32(pa0.w);
        As[buf][ac + 4][ar] = f2tf32(pa1.x); As[buf][ac + 5][ar] = f2tf32(pa1.y);
        As[buf][ac + 6][ar] = f2tf32(pa1.z); As[buf][ac + 7][ar] = f2tf32(pa1.w);
        uint4 u0 = make_uint4(f2tf32(pb0.x), f2tf32(pb0.y), f2tf32(pb0.z), f2tf32(pb0.w));
        uint4 u1 = make_uint4(f2tf32(pb1.x), f2tf32(pb1.y), f2tf32(pb1.z), f2tf32(pb1.w));
        *(uint4*)&Bs[buf][bk][bn]     = u0;
        *(uint4*)&Bs[buf][bk][bn + 4] = u1;
        __syncthreads();

        if (t + 1 < T) {   // prefetch next tile (overlaps mma)
            int kn = (t + 1) * 16;
            pa0 = *(const float4*)(Ap + kn);
            pa1 = *(const float4*)(Ap + kn + 4);
            const float* bp = Bp + (size_t)kn * N;
            pb0 = *(const float4*)(bp);
            pb1 = *(const float4*)(bp + 4);
        }

#pragma unroll
        for (int ks = 0; ks < 2; ks++) {
            int kb = ks * 8;
            unsigned af[4][4], bf[4][2];
#pragma unroll
            for (int mt = 0; mt < 4; mt++) {
                int row = wm + mt * 16 + grp;
                af[mt][0] = As[buf][kb + tig][row];
                af[mt][1] = As[buf][kb + tig][row + 8];
                af[mt][2] = As[buf][kb + tig + 4][row];
                af[mt][3] = As[buf][kb + tig + 4][row + 8];
            }
#pragma unroll
            for (int nt = 0; nt < 4; nt++) {
                int col = wn + nt * 8 + grp;
                bf[nt][0] = Bs[buf][kb + tig][col];
                bf[nt][1] = Bs[buf][kb + tig + 4][col];
            }
#pragma unroll
            for (int mt = 0; mt < 4; mt++)
#pragma unroll
                for (int nt = 0; nt < 4; nt++)
                    mma16n8k8(c[mt][nt], af[mt], bf[nt]);
        }
        // no trailing barrier: next iteration's STS targets the other buffer
    }

#pragma unroll
    for (int mt = 0; mt < 4; mt++) {
        int r0 = m0 + wm + mt * 16 + grp;
#pragma unroll
        for (int nt = 0; nt < 4; nt++) {
            int col = n0 + wn + nt * 8 + tig * 2;
            float2 bv = *(const float2*)(bias + col);
            *(float2*)(C + (size_t)r0 * N + col) =
                make_float2(c[mt][nt][0] + bv.x, c[mt][nt][1] + bv.y);
            *(float2*)(C + (size_t)(r0 + 8) * N + col) =
                make_float2(c[mt][nt][2] + bv.x, c[mt][nt][3] + bv.y);
        }
    }
}

// ---------------------------------------------------------------------------
// Fused attention: scores + softmax + AV (unchanged from R5).
// ---------------------------------------------------------------------------
__global__ __launch_bounds__(256, 2) void attn_fused(
    const float* __restrict__ qkv, float* __restrict__ w,
    float* __restrict__ ctx)
{
    __shared__ unsigned Ks[64][68];
    __shared__ unsigned Vs[64][72];

    int tid = threadIdx.x, lane = tid & 31, wid = tid >> 5;
    int grp = lane >> 2, tig = lane & 3;
    int qt = 7 - blockIdx.x;
    int q0 = qt * 128;
    int ntiles = qt * 2 + 2;
    int bh = blockIdx.y;
    int b = bh >> 4, h = bh & 15;

    int row0 = wid * 16 + grp;
    int gq0 = q0 + row0, gq1 = gq0 + 8;

    const float* Q0 = qkv + (size_t)(b * PS + gq0) * QKV_N + h * PHD;
    const float* Q1 = Q0 + 8 * QKV_N;
    unsigned qa[8][4];
#pragma unroll
    for (int kd = 0; kd < 8; kd++) {
        qa[kd][0] = f2tf32(Q0[kd * 8 + tig] * 0.125f);
        qa[kd][1] = f2tf32(Q1[kd * 8 + tig] * 0.125f);
        qa[kd][2] = f2tf32(Q0[kd * 8 + tig + 4] * 0.125f);
        qa[kd][3] = f2tf32(Q1[kd * 8 + tig + 4] * 0.125f);
    }

    int kr = tid >> 2, kc = (tid & 3) * 16;
    const float* Kb = qkv + (size_t)(b * PS + kr) * QKV_N + PD + h * PHD + kc;
    const float* Vb = Kb + PD;

    float m0 = -INFINITY, m1 = -INFINITY, l0 = 0.f, l1 = 0.f;

    // ---------------- Pass 1: row stats ----------------
    float4 pk[4];
#pragma unroll
    for (int i = 0; i < 4; i++) pk[i] = *(const float4*)(Kb + i * 4);

    for (int t = 0; t < ntiles; t++) {
#pragma unroll
        for (int i = 0; i < 4; i++) {
            Ks[kr][kc + i * 4 + 0] = f2tf32(pk[i].x);
            Ks[kr][kc + i * 4 + 1] = f2tf32(pk[i].y);
            Ks[kr][kc + i * 4 + 2] = f2tf32(pk[i].z);
            Ks[kr][kc + i * 4 + 3] = f2tf32(pk[i].w);
        }
        __syncthreads();
        if (t + 1 < ntiles) {
#pragma unroll
            for (int i = 0; i < 4; i++)
                pk[i] = *(const float4*)(Kb + (size_t)(t + 1) * 64 * QKV_N + i * 4);
        }

        float c[8][4];
#pragma unroll
        for (int nt = 0; nt < 8; nt++)
#pragma unroll
            for (int i = 0; i < 4; i++) c[nt][i] = 0.f;
#pragma unroll
        for (int kd = 0; kd < 8; kd++) {
            int kb = kd * 8;
#pragma unroll
            for (int nt = 0; nt < 8; nt++) {
                unsigned bf[2] = { Ks[nt * 8 + grp][kb + tig],
                                   Ks[nt * 8 + grp][kb + tig + 4] };
                mma16n8k8(c[nt], qa[kd], bf);
            }
        }

        int kt0 = t * 64;
        if (t + 2 >= ntiles) {
#pragma unroll
            for (int nt = 0; nt < 8; nt++) {
                int cc = kt0 + nt * 8 + tig * 2;
                if (cc > gq0)     c[nt][0] = -INFINITY;
                if (cc + 1 > gq0) c[nt][1] = -INFINITY;
                if (cc > gq1)     c[nt][2] = -INFINITY;
                if (cc + 1 > gq1) c[nt][3] = -INFINITY;
            }
        }

        float tm0 = -INFINITY, tm1 = -INFINITY;
#pragma unroll
        for (int nt = 0; nt < 8; nt++) {
            tm0 = fmaxf(tm0, fmaxf(c[nt][0], c[nt][1]));
            tm1 = fmaxf(tm1, fmaxf(c[nt][2], c[nt][3]));
        }
        tm0 = qmax(tm0); tm1 = qmax(tm1);
        float nm0 = fmaxf(m0, tm0), nm1 = fmaxf(m1, tm1);
        float s0 = 0.f, s1 = 0.f;
#pragma unroll
        for (int nt = 0; nt < 8; nt++) {
            s0 += __expf(c[nt][0] - nm0) + __expf(c[nt][1] - nm0);
            s1 += __expf(c[nt][2] - nm1) + __expf(c[nt][3] - nm1);
        }
        s0 = qsum(s0); s1 = qsum(s1);
        l0 = l0 * __expf(m0 - nm0) + s0;
        l1 = l1 * __expf(m1 - nm1) + s1;
        m0 = nm0; m1 = nm1;
        __syncthreads();
    }

    float inv0 = 1.f / l0, inv1 = 1.f / l1;

    // ---------------- Pass 2: emit weights + AV ----------------
    float o[8][4];
#pragma unroll
    for (int nt = 0; nt < 8; nt++)
#pragma unroll
        for (int i = 0; i < 4; i++) o[nt][i] = 0.f;

    float* wr0 = w + (size_t)(bh * PS + gq0) * PS;
    float* wr1 = wr0 + 8 * PS;
    int base = lane & ~3;

    for (int t = 0; t < ntiles; t++) {
#pragma unroll
        for (int i = 0; i < 4; i++) {
            float4 kv = *(const float4*)(Kb + (size_t)t * 64 * QKV_N + i * 4);
            float4 vv = *(const float4*)(Vb + (size_t)t * 64 * QKV_N + i * 4);
            Ks[kr][kc + i * 4 + 0] = f2tf32(kv.x);
            Ks[kr][kc + i * 4 + 1] = f2tf32(kv.y);
            Ks[kr][kc + i * 4 + 2] = f2tf32(kv.z);
            Ks[kr][kc + i * 4 + 3] = f2tf32(kv.w);
            Vs[kr][kc + i * 4 + 0] = f2tf32(vv.x);
            Vs[kr][kc + i * 4 + 1] = f2tf32(vv.y);
            Vs[kr][kc + i * 4 + 2] = f2tf32(vv.z);
            Vs[kr][kc + i * 4 + 3] = f2tf32(vv.w);
        }
        __syncthreads();

        float c[8][4];
#pragma unroll
        for (int nt = 0; nt < 8; nt++)
#pragma unroll
            for (int i = 0; i < 4; i++) c[nt][i] = 0.f;
#pragma unroll
        for (int kd = 0; kd < 8; kd++) {
            int kb = kd * 8;
#pragma unroll
            for (int nt = 0; nt < 8; nt++) {
                unsigned bf[2] = { Ks[nt * 8 + grp][kb + tig],
                                   Ks[nt * 8 + grp][kb + tig + 4] };
                mma16n8k8(c[nt], qa[kd], bf);
            }
        }

        int kt0 = t * 64;
        bool diag = (t + 2 >= ntiles);

#pragma unroll
        for (int nt = 0; nt < 8; nt++) {
            int cc = kt0 + nt * 8 + tig * 2;
            float p0 = __expf(c[nt][0] - m0) * inv0;
            float p1 = __expf(c[nt][1] - m0) * inv0;
            float p2 = __expf(c[nt][2] - m1) * inv1;
            float p3 = __expf(c[nt][3] - m1) * inv1;
            if (diag) {
                if (cc > gq0)     p0 = 0.f;
                if (cc + 1 > gq0) p1 = 0.f;
                if (cc > gq1)     p2 = 0.f;
                if (cc + 1 > gq1) p3 = 0.f;
            }
            *(float2*)(wr0 + cc) = make_float2(p0, p1);
            *(float2*)(wr1 + cc) = make_float2(p2, p3);

            unsigned u0 = f2tf32(p0), u1 = f2tf32(p1);
            unsigned u2 = f2tf32(p2), u3 = f2tf32(p3);
            int s0l = base + (tig >> 1);
            int s1l = s0l + 2;
            unsigned e0 = __shfl_sync(0xffffffffu, u0, s0l);
            unsigned f0 = __shfl_sync(0xffffffffu, u1, s0l);
            unsigned e1 = __shfl_sync(0xffffffffu, u2, s0l);
            unsigned f1 = __shfl_sync(0xffffffffu, u3, s0l);
            unsigned e2 = __shfl_sync(0xffffffffu, u0, s1l);
            unsigned f2 = __shfl_sync(0xffffffffu, u1, s1l);
            unsigned e3 = __shfl_sync(0xffffffffu, u2, s1l);
            unsigned f3 = __shfl_sync(0xffffffffu, u3, s1l);
            bool odd = (tig & 1);
            unsigned a[4];
            a[0] = odd ? f0 : e0;
            a[1] = odd ? f1 : e1;
            a[2] = odd ? f2 : e2;
            a[3] = odd ? f3 : e3;

#pragma unroll
            for (int ntd = 0; ntd < 8; ntd++) {
                unsigned bf[2] = { Vs[nt * 8 + tig][ntd * 8 + grp],
                                   Vs[nt * 8 + tig + 4][ntd * 8 + grp] };
                mma16n8k8(o[ntd], a, bf);
            }
        }
        __syncthreads();
    }

    float* c0p = ctx + (size_t)(b * PS + gq0) * PD + h * PHD;
    float* c1p = c0p + 8 * PD;
#pragma unroll
    for (int ntd = 0; ntd < 8; ntd++) {
        int col = ntd * 8 + tig * 2;
        *(float2*)(c0p + col) = make_float2(o[ntd][0], o[ntd][1]);
        *(float2*)(c1p + col) = make_float2(o[ntd][2], o[ntd][3]);
    }

    int zc = q0 + 128;
    int nz4 = (PS - zc) >> 2;
    if (nz4 > 0) {
        float4 z = make_float4(0.f, 0.f, 0.f, 0.f);
        for (int i = tid; i < 128 * nz4; i += 256) {
            int r = i / nz4, c4 = i - r * nz4;
            *(float4*)(w + (size_t)(bh * PS + q0 + r) * PS + zc + c4 * 4) = z;
        }
    }
}

// ---------------------------------------------------------------------------
extern "C" void kernel_launch(void* const* d_in, const int* in_sizes, int n_in,
                              void* d_out, int out_size)
{
    const float* hidden = (const float*)d_in[0];
    const float* W_attn = (const float*)d_in[1];
    const float* b_attn = (const float*)d_in[2];
    const float* W_proj = (const float*)d_in[3];
    const float* b_proj = (const float*)d_in[4];
    float* out = (float*)d_out;

    float *qkv, *ctx, *wscr;
    cudaGetSymbolAddress((void**)&qkv, g_qkv);
    cudaGetSymbolAddress((void**)&ctx, g_ctx);
    cudaGetSymbolAddress((void**)&wscr, g_wscratch);

    float* attn_out = out;
    float* wptr;
    if ((unsigned long long)out_size >= ATTN_OUT_ELEMS + ATTN_W_ELEMS) {
        wptr = out + ATTN_OUT_ELEMS;
    } else if ((unsigned long long)out_size == ATTN_W_ELEMS) {
        wptr = out;
        attn_out = ctx;
    } else {
        wptr = wscr;
    }

    sgemm_tf32<<<dim3(QKV_N / 128, BS / 128), 256>>>(
        hidden, W_attn, b_attn, qkv, BS, QKV_N, PD);

    attn_fused<<<dim3(8, PB * PH), 256>>>(qkv, wptr, ctx);

    sgemm_tf32<<<dim3(PD / 128, BS / 128), 256>>>(
        ctx, W_proj, b_proj, attn_out, BS, PD, PD);
}